// round 7
// baseline (speedup 1.0000x reference)
#include <cuda_runtime.h>
#include <stdint.h>

#define Bn 32
#define Nn 512
#define Pn 128
#define CAP 64           // max nonzeros per (128-row chunk, column); mean ~15

// Scratch (static device globals: allocation-free)
__device__ float g_mw[Bn * Nn * Pn];                    // mu @ W2 (8 MB)
__device__ unsigned char g_idx[Bn * 4 * Nn * CAP];      // CSR lists (4 MB)
__device__ int   g_cnt[Bn * 4 * Nn];                    // counts
__device__ float2 g_pnc[Bn * 4 * Nn];                   // per-chunk (pos,neg)
__device__ float g_vp[Pn];
__device__ float g_vn[Pn];
__device__ float g_cb[Pn];

// ---- packed f32x2 helpers (PTX-only packed-FP32 pipe) ---------------------
__device__ __forceinline__ void fma2(unsigned long long& d,
                                     unsigned long long a,
                                     unsigned long long b) {
    asm("fma.rn.f32x2 %0, %1, %2, %3;" : "=l"(d) : "l"(a), "l"(b), "l"(d));
}
__device__ __forceinline__ void add2(unsigned long long& d,
                                     unsigned long long v) {
    asm("add.rn.f32x2 %0, %1, %2;" : "=l"(d) : "l"(d), "l"(v));
}
__device__ __forceinline__ unsigned long long rep2(float a) {
    unsigned long long p;
    asm("mov.b64 %0, {%1, %1};" : "=l"(p) : "f"(a));
    return p;
}
__device__ __forceinline__ float2 unpack2(unsigned long long p) {
    float2 r;
    asm("mov.b64 {%0, %1}, %2;" : "=f"(r.x), "=f"(r.y) : "l"(p));
    return r;
}

// ---------------------------------------------------------------------------
// Phase 1 (heterogeneous, 1281 CTAs x 256 threads):
//   bid%5 != 4 (bid<1280): CSR build for one (b, j-tile, i-chunk) 128x64 tile
//   bid%5 == 4 (bid<1280): mu @ W2 GEMM tile (64 rows)
//   bid == 1280:           prep (vp/vn/cb)
// ---------------------------------------------------------------------------
__global__ __launch_bounds__(256) void phase1_kernel(
    const float* __restrict__ mu, const float* __restrict__ W2,
    const float* __restrict__ W3, const float* __restrict__ theta4,
    const float* __restrict__ b1, const float* __restrict__ b2,
    const float* __restrict__ b3,
    const float* __restrict__ adj, const float* __restrict__ weight) {
    int bid = blockIdx.x;
    int tid = threadIdx.x;

    if (bid == 1280) {
        int p = tid;
        if (p < Pn) {
            float vp = 0.f, vn = 0.f;
            #pragma unroll 8
            for (int q = 0; q < Pn; ++q) {
                float t = theta4[q];
                float w = W3[q * Pn + p];
                vp += fmaxf(t, 0.f) * w;
                vn += fmaxf(-t, 0.f) * w;
            }
            g_vp[p] = vp;
            g_vn[p] = vn;
            g_cb[p] = b1[p] + b2[p] + b3[p];
        }
        return;
    }

    int g5 = bid / 5;
    int r5 = bid % 5;

    if (r5 != 4) {
        // ===== CSR build for one 128x64 tile: idx = g5*4 + r5 (0..1023) ====
        __shared__ char bsm[12800];                    // adjB 8704 | Ls 4096
        unsigned char* adjB = (unsigned char*)bsm;     // [128][68]
        unsigned char* Ls   = (unsigned char*)(bsm + 8704);  // [64][64]

        int idx = g5 * 4 + r5;
        int b = idx >> 5;
        int rem = idx & 31;
        int j0 = (rem >> 2) * 64;
        int chunk = rem & 3;
        int i0 = chunk * 128;

        int warp = tid >> 5, lane = tid & 31;
        int rg = tid >> 4;             // row-group 0..15
        int jc = tid & 15;             // fixed 4-column group
        const float* adj_b = adj + (size_t)b * Nn * Nn;
        const float* w_b   = weight + (size_t)b * Nn * Nn;

        float pr[4] = {0.f, 0.f, 0.f, 0.f};
        float nr[4] = {0.f, 0.f, 0.f, 0.f};

        // Stream adj+weight tile (coalesced float4); indicator bytes to smem
        #pragma unroll
        for (int s = 0; s < 8; ++s) {
            int row = rg + s * 16;
            size_t g = (size_t)(i0 + row) * Nn + j0 + jc * 4;
            float4 a = *(const float4*)&adj_b[g];
            float4 w = *(const float4*)&w_b[g];
            uchar4 ab;
            ab.x = (a.x != 0.f);
            ab.y = (a.y != 0.f);
            ab.z = (a.z != 0.f);
            ab.w = (a.w != 0.f);
            *(uchar4*)&adjB[row * 68 + jc * 4] = ab;
            pr[0] += a.x * fmaxf(w.x, 0.f);  nr[0] += a.x * fmaxf(-w.x, 0.f);
            pr[1] += a.y * fmaxf(w.y, 0.f);  nr[1] += a.y * fmaxf(-w.y, 0.f);
            pr[2] += a.z * fmaxf(w.z, 0.f);  nr[2] += a.z * fmaxf(-w.z, 0.f);
            pr[3] += a.w * fmaxf(w.w, 0.f);  nr[3] += a.w * fmaxf(-w.w, 0.f);
        }
        __syncthreads();

        // Compaction scan: 8 warps x 8 columns -> smem lists
        #pragma unroll
        for (int cc = 0; cc < 8; ++cc) {
            int j = warp * 8 + cc;
            int run = 0;
            #pragma unroll
            for (int base = 0; base < 128; base += 32) {
                unsigned char av = adjB[(base + lane) * 68 + j];
                unsigned m = __ballot_sync(0xffffffffu, av != 0);
                if (av)
                    Ls[(j << 6) + run + __popc(m & ((1u << lane) - 1u))] =
                        (unsigned char)(base + lane);
                run += __popc(m);
            }
            if (lane == 0) g_cnt[(b * 4 + chunk) * Nn + j0 + j] = run;
        }
        __syncthreads();

        // Copy lists out (coalesced uint4): 256 threads = 64 j x 4 parts
        {
            int j = tid >> 2;
            int part = tid & 3;
            *(uint4*)&g_idx[(((size_t)(b * 4 + chunk) * Nn + j0 + j) << 6) + (part << 4)] =
                *(const uint4*)&Ls[(j << 6) + (part << 4)];
        }
        __syncthreads();   // Ls/adjB dead; pbuf overlays

        // Deterministic per-chunk pos/neg reduction
        float* pbuf = (float*)bsm;       // 2 x 1024 floats = 8 KB
        #pragma unroll
        for (int cc = 0; cc < 4; ++cc) {
            pbuf[rg * 64 + jc * 4 + cc]        = pr[cc];
            pbuf[1024 + rg * 64 + jc * 4 + cc] = nr[cc];
        }
        __syncthreads();
        if (tid < 64) {
            float sp = 0.f, sn = 0.f;
            #pragma unroll
            for (int g = 0; g < 16; ++g) {
                sp += pbuf[g * 64 + tid];
                sn += pbuf[1024 + g * 64 + tid];
            }
            g_pnc[(b * 4 + chunk) * Nn + j0 + tid] = make_float2(sp, sn);
        }
        return;
    }

    // ============ GEMM tile: g_mw[r0..r0+64) = mu @ W2 =====================
    __shared__ float As[32 * 68];
    __shared__ float Bs[32 * 128];
    int r0 = g5 * 64;
    int tx = tid & 15;
    int ty = tid >> 4;

    unsigned long long acc2[4][4];
    #pragma unroll
    for (int u = 0; u < 4; ++u)
        #pragma unroll
        for (int q = 0; q < 4; ++q) acc2[u][q] = 0ull;

    for (int kb = 0; kb < 4; ++kb) {
        int k0 = kb * 32;
        #pragma unroll
        for (int s = 0; s < 2; ++s) {
            int idx = tid + s * 256;
            int m = idx >> 3;
            int kq = idx & 7;
            float4 f = *(const float4*)&mu[(r0 + m) * Pn + k0 + kq * 4];
            As[(kq * 4 + 0) * 68 + m] = f.x;
            As[(kq * 4 + 1) * 68 + m] = f.y;
            As[(kq * 4 + 2) * 68 + m] = f.z;
            As[(kq * 4 + 3) * 68 + m] = f.w;
        }
        #pragma unroll
        for (int s = 0; s < 4; ++s) {
            int idx = tid + s * 256;
            int k = idx >> 5;
            int c = idx & 31;
            *(float4*)&Bs[k * 128 + c * 4] =
                *(const float4*)&W2[(k0 + k) * Pn + c * 4];
        }
        __syncthreads();

        #pragma unroll
        for (int k = 0; k < 32; ++k) {
            float4 a4 = *(const float4*)&As[k * 68 + ty * 4];
            ulonglong2 B0 = *(const ulonglong2*)&Bs[k * 128 + tx * 8];
            ulonglong2 B1 = *(const ulonglong2*)&Bs[k * 128 + tx * 8 + 4];
            unsigned long long pa[4] = {rep2(a4.x), rep2(a4.y), rep2(a4.z), rep2(a4.w)};
            #pragma unroll
            for (int u = 0; u < 4; ++u) {
                fma2(acc2[u][0], pa[u], B0.x);
                fma2(acc2[u][1], pa[u], B0.y);
                fma2(acc2[u][2], pa[u], B1.x);
                fma2(acc2[u][3], pa[u], B1.y);
            }
        }
        __syncthreads();
    }

    #pragma unroll
    for (int u = 0; u < 4; ++u) {
        int row = r0 + ty * 4 + u;
        ulonglong2 o0 = {acc2[u][0], acc2[u][1]};
        ulonglong2 o1 = {acc2[u][2], acc2[u][3]};
        *(ulonglong2*)&g_mw[row * Pn + tx * 8]     = o0;
        *(ulonglong2*)&g_mw[row * Pn + tx * 8 + 4] = o1;
    }
}

// ---------------------------------------------------------------------------
// Phase 2: CSR-driven gather + epilogue. Two independent add2 chains.
// ---------------------------------------------------------------------------
__global__ __launch_bounds__(512, 2) void agg_kernel(
    const float* __restrict__ x, const float* __restrict__ W1,
    float* __restrict__ out) {
    extern __shared__ char smem[];
    float* mwS = (float*)smem;                              // 65536 B
    unsigned char* idxS = (unsigned char*)(smem + 65536);   // 64*64 B
    int*   cntS = (int*)(smem + 69632);                     // 64 ints
    float* W1s  = (float*)(smem + 69888);
    float* vps  = W1s + 128;
    float* vns  = vps + 128;
    float* cbs  = vns + 128;

    int tid = threadIdx.x;
    int warp = tid >> 5;
    int lane = tid & 31;
    int b = blockIdx.y;
    int j0 = blockIdx.x * 64;

    if (tid < 128) {
        W1s[tid] = W1[tid];
        vps[tid] = g_vp[tid];
        vns[tid] = g_vn[tid];
        cbs[tid] = g_cb[tid];
    }

    const float* mw_b = g_mw + (size_t)b * Nn * Pn;
    int lane4 = lane << 2;

    unsigned long long acc2[4][2];
    #pragma unroll
    for (int jj = 0; jj < 4; ++jj) { acc2[jj][0] = 0ull; acc2[jj][1] = 0ull; }

    for (int chunk = 0; chunk < 4; ++chunk) {
        __syncthreads();

        int i0 = chunk * 128;
        #pragma unroll
        for (int s = 0; s < 8; ++s) {
            int idx = tid + s * 512;
            int row = idx >> 5;
            int c = idx & 31;
            *(float4*)&mwS[row * 128 + c * 4] =
                *(const float4*)&mw_b[(i0 + row) * Pn + c * 4];
        }
        if (tid < 256) {
            int j = tid >> 2;
            int part = tid & 3;
            *(uint4*)&idxS[(j << 6) + (part << 4)] =
                *(const uint4*)&g_idx[(((size_t)(b * 4 + chunk) * Nn + j0 + j) << 6) + (part << 4)];
        }
        if (tid >= 448) {
            int t2 = tid - 448;
            cntS[t2] = g_cnt[(b * 4 + chunk) * Nn + j0 + t2];
        }
        __syncthreads();

        #pragma unroll
        for (int jj = 0; jj < 4; ++jj) {
            int j = warp * 4 + jj;
            int n = cntS[j];
            const unsigned char* L = idxS + (j << 6);
            unsigned long long a0 = acc2[jj][0], a1 = acc2[jj][1];
            unsigned long long c0 = 0ull, c1 = 0ull;   // second chain
            int k = 0;
            for (; k + 4 <= n; k += 4) {
                unsigned q = *(const unsigned*)(L + k);
                int i0x = q & 255, i1x = (q >> 8) & 255,
                    i2x = (q >> 16) & 255, i3x = q >> 24;
                ulonglong2 v0 = *(const ulonglong2*)&mwS[i0x * 128 + lane4];
                ulonglong2 v1 = *(const ulonglong2*)&mwS[i1x * 128 + lane4];
                ulonglong2 v2 = *(const ulonglong2*)&mwS[i2x * 128 + lane4];
                ulonglong2 v3 = *(const ulonglong2*)&mwS[i3x * 128 + lane4];
                add2(a0, v0.x); add2(a1, v0.y);
                add2(c0, v1.x); add2(c1, v1.y);
                add2(a0, v2.x); add2(a1, v2.y);
                add2(c0, v3.x); add2(c1, v3.y);
            }
            for (; k < n; ++k) {
                int i = L[k];
                ulonglong2 v = *(const ulonglong2*)&mwS[i * 128 + lane4];
                add2(a0, v.x); add2(a1, v.y);
            }
            add2(a0, c0); add2(a1, c1);
            acc2[jj][0] = a0; acc2[jj][1] = a1;
        }
    }

    #pragma unroll
    for (int jj = 0; jj < 4; ++jj) {
        int gj = j0 + warp * 4 + jj;
        float xv = x[b * Nn + gj];
        float pj = 0.f, nj = 0.f;
        #pragma unroll
        for (int c = 0; c < 4; ++c) {
            float2 pn = g_pnc[(b * 4 + c) * Nn + gj];
            pj += pn.x;
            nj += pn.y;
        }
        int p = lane4;
        float2 u0 = unpack2(acc2[jj][0]);
        float2 u1 = unpack2(acc2[jj][1]);
        float4 o;
        o.x = fmaxf(xv * W1s[p + 0] + u0.x + pj * vps[p + 0] + nj * vns[p + 0] + cbs[p + 0], 0.f);
        o.y = fmaxf(xv * W1s[p + 1] + u0.y + pj * vps[p + 1] + nj * vns[p + 1] + cbs[p + 1], 0.f);
        o.z = fmaxf(xv * W1s[p + 2] + u1.x + pj * vps[p + 2] + nj * vns[p + 2] + cbs[p + 2], 0.f);
        o.w = fmaxf(xv * W1s[p + 3] + u1.y + pj * vps[p + 3] + nj * vns[p + 3] + cbs[p + 3], 0.f);
        *(float4*)&out[((size_t)b * Nn + gj) * Pn + p] = o;
    }
}

// ---------------------------------------------------------------------------
extern "C" void kernel_launch(void* const* d_in, const int* in_sizes, int n_in,
                              void* d_out, int out_size) {
    const float* x      = (const float*)d_in[0];
    const float* mu     = (const float*)d_in[1];
    const float* weight = (const float*)d_in[2];
    const float* adj    = (const float*)d_in[3];
    const float* W1     = (const float*)d_in[4];
    const float* b1     = (const float*)d_in[5];
    const float* W2     = (const float*)d_in[6];
    const float* b2     = (const float*)d_in[7];
    const float* W3     = (const float*)d_in[8];
    const float* b3     = (const float*)d_in[9];
    const float* theta4 = (const float*)d_in[10];
    float* out = (float*)d_out;

    const int smem_bytes = 69888 + 4 * 128 * 4;   // 71936 B
    static int configured = -1;
    if (configured < 0) {
        cudaFuncSetAttribute(agg_kernel, cudaFuncAttributeMaxDynamicSharedMemorySize,
                             smem_bytes);
        configured = 1;
    }

    phase1_kernel<<<1281, 256>>>(mu, W2, W3, theta4, b1, b2, b3, adj, weight);
    dim3 grid(Nn / 64, Bn);
    agg_kernel<<<grid, 512, smem_bytes>>>(x, W1, out);
}

// round 8
// speedup vs baseline: 1.1823x; 1.1823x over previous
#include <cuda_runtime.h>
#include <stdint.h>

#define Bn 32
#define Nn 512
#define Pn 128

// Scratch (static device globals: allocation-free)
__device__ float g_mw[Bn * Nn * Pn];   // mu @ W2 (8 MB)
__device__ float g_vp[Pn];
__device__ float g_vn[Pn];
__device__ float g_cb[Pn];             // b1 + b2 + b3

// ---- packed f32x2 helpers (PTX-only packed-FP32 pipe) ---------------------
__device__ __forceinline__ void fma2(unsigned long long& d,
                                     unsigned long long a,
                                     unsigned long long b) {
    asm("fma.rn.f32x2 %0, %1, %2, %3;" : "=l"(d) : "l"(a), "l"(b), "l"(d));
}
__device__ __forceinline__ void add2(unsigned long long& d,
                                     unsigned long long v) {
    asm("add.rn.f32x2 %0, %1, %2;" : "=l"(d) : "l"(d), "l"(v));
}
__device__ __forceinline__ unsigned long long rep2(float a) {
    unsigned long long p;
    asm("mov.b64 %0, {%1, %1};" : "=l"(p) : "f"(a));
    return p;
}
__device__ __forceinline__ float2 unpack2(unsigned long long p) {
    float2 r;
    asm("mov.b64 {%0, %1}, %2;" : "=f"(r.x), "=f"(r.y) : "l"(p));
    return r;
}

// ---------------------------------------------------------------------------
// Phase 1: mu @ W2 GEMM (256 CTAs) + prep (last CTA). fp32 via f32x2.
// ---------------------------------------------------------------------------
__global__ __launch_bounds__(256) void mw_kernel(const float* __restrict__ mu,
                                                 const float* __restrict__ W2,
                                                 const float* __restrict__ W3,
                                                 const float* __restrict__ theta4,
                                                 const float* __restrict__ b1,
                                                 const float* __restrict__ b2,
                                                 const float* __restrict__ b3) {
    if (blockIdx.x == gridDim.x - 1) {
        int p = threadIdx.x;
        if (p < Pn) {
            float vp = 0.f, vn = 0.f;
            #pragma unroll 8
            for (int q = 0; q < Pn; ++q) {
                float t = theta4[q];
                float w = W3[q * Pn + p];
                vp += fmaxf(t, 0.f) * w;
                vn += fmaxf(-t, 0.f) * w;
            }
            g_vp[p] = vp;
            g_vn[p] = vn;
            g_cb[p] = b1[p] + b2[p] + b3[p];
        }
        return;
    }

    __shared__ float As[32 * 68];
    __shared__ float Bs[32 * 128];

    int tid = threadIdx.x;
    int tx = tid & 15;
    int ty = tid >> 4;
    int r0 = blockIdx.x * 64;

    unsigned long long acc2[4][4];
    #pragma unroll
    for (int u = 0; u < 4; ++u)
        #pragma unroll
        for (int q = 0; q < 4; ++q) acc2[u][q] = 0ull;

    for (int kb = 0; kb < 4; ++kb) {
        int k0 = kb * 32;
        #pragma unroll
        for (int s = 0; s < 2; ++s) {
            int idx = tid + s * 256;
            int m = idx >> 3;
            int kq = idx & 7;
            float4 f = *(const float4*)&mu[(r0 + m) * Pn + k0 + kq * 4];
            As[(kq * 4 + 0) * 68 + m] = f.x;
            As[(kq * 4 + 1) * 68 + m] = f.y;
            As[(kq * 4 + 2) * 68 + m] = f.z;
            As[(kq * 4 + 3) * 68 + m] = f.w;
        }
        #pragma unroll
        for (int s = 0; s < 4; ++s) {
            int idx = tid + s * 256;
            int k = idx >> 5;
            int c = idx & 31;
            *(float4*)&Bs[k * 128 + c * 4] =
                *(const float4*)&W2[(k0 + k) * Pn + c * 4];
        }
        __syncthreads();

        #pragma unroll
        for (int k = 0; k < 32; ++k) {
            float4 a4 = *(const float4*)&As[k * 68 + ty * 4];
            ulonglong2 B0 = *(const ulonglong2*)&Bs[k * 128 + tx * 8];
            ulonglong2 B1 = *(const ulonglong2*)&Bs[k * 128 + tx * 8 + 4];
            unsigned long long pa[4] = {rep2(a4.x), rep2(a4.y), rep2(a4.z), rep2(a4.w)};
            #pragma unroll
            for (int u = 0; u < 4; ++u) {
                fma2(acc2[u][0], pa[u], B0.x);
                fma2(acc2[u][1], pa[u], B0.y);
                fma2(acc2[u][2], pa[u], B1.x);
                fma2(acc2[u][3], pa[u], B1.y);
            }
        }
        __syncthreads();
    }

    #pragma unroll
    for (int u = 0; u < 4; ++u) {
        int row = r0 + ty * 4 + u;
        ulonglong2 o0 = {acc2[u][0], acc2[u][1]};
        ulonglong2 o1 = {acc2[u][2], acc2[u][3]};
        *(ulonglong2*)&g_mw[row * Pn + tx * 8]     = o0;
        *(ulonglong2*)&g_mw[row * Pn + tx * 8 + 4] = o1;
    }
}

// ---------------------------------------------------------------------------
// Phase 2: fused stream + in-CTA compaction + quad gather + epilogue.
// Grid (8 j-tiles, 32 b), 512 threads = 16 warps; warp owns 4 j columns.
// Per 128-i chunk: stage mw + adj/weight (pos/neg reg partials, indicator
// bytes) -> warp ballot-scan own columns into smem lists -> pipelined gather.
// smem: mwS 64K | adjB 8.5K | Ls 4K | consts 2.5K  (~79KB -> 2 CTA/SM)
// ---------------------------------------------------------------------------
__global__ __launch_bounds__(512, 2) void agg_kernel(
    const float* __restrict__ adj, const float* __restrict__ weight,
    const float* __restrict__ x, const float* __restrict__ W1,
    float* __restrict__ out) {
    extern __shared__ char smem[];
    float* mwS = (float*)smem;                              // 65536 B
    unsigned char* adjB = (unsigned char*)(smem + 65536);   // [128][68]
    unsigned char* Ls   = (unsigned char*)(smem + 74240);   // [64][64]
    float* W1s  = (float*)(smem + 78336);                   // 128
    float* vps  = W1s + 128;
    float* vns  = vps + 128;
    float* cbs  = vns + 128;
    float* posS = cbs + 128;                                // 64
    float* negS = posS + 64;                                // 64
    float* pbuf = (float*)smem;                             // overlay (final)

    int tid = threadIdx.x;
    int warp = tid >> 5;
    int lane = tid & 31;
    int b = blockIdx.y;
    int j0 = blockIdx.x * 64;

    if (tid < 128) {
        W1s[tid] = W1[tid];
        vps[tid] = g_vp[tid];
        vns[tid] = g_vn[tid];
        cbs[tid] = g_cb[tid];
    }

    const float* adj_b = adj + (size_t)b * Nn * Nn;
    const float* w_b   = weight + (size_t)b * Nn * Nn;
    const float* mw_b  = g_mw + (size_t)b * Nn * Pn;
    int lane4 = lane << 2;
    int jc = tid & 15;     // fixed 4-column group for staging/pos-neg

    unsigned long long acc2[4][2];
    float posr[4], negr[4];
    #pragma unroll
    for (int jj = 0; jj < 4; ++jj) {
        acc2[jj][0] = 0ull;
        acc2[jj][1] = 0ull;
        posr[jj] = 0.f;
        negr[jj] = 0.f;
    }

    for (int chunk = 0; chunk < 4; ++chunk) {
        int i0 = chunk * 128;
        __syncthreads();   // prev chunk smem reads done (covers const init)

        // --- Stage mw chunk (128 x 128 f32, coalesced float4) ---
        #pragma unroll
        for (int s = 0; s < 8; ++s) {
            int idx = tid + s * 512;
            int row = idx >> 5;
            int c = idx & 31;
            *(float4*)&mwS[row * 128 + c * 4] =
                *(const float4*)&mw_b[(i0 + row) * Pn + c * 4];
        }
        // --- Stream adj+weight tile; pos/neg partials; indicator bytes ---
        #pragma unroll
        for (int s = 0; s < 4; ++s) {
            int idx = tid + s * 512;
            int row = idx >> 4;
            size_t g = (size_t)(i0 + row) * Nn + j0 + jc * 4;
            float4 a = *(const float4*)&adj_b[g];
            float4 w = *(const float4*)&w_b[g];
            uchar4 ab;
            ab.x = (a.x != 0.f);
            ab.y = (a.y != 0.f);
            ab.z = (a.z != 0.f);
            ab.w = (a.w != 0.f);
            *(uchar4*)&adjB[row * 68 + jc * 4] = ab;
            // adj is exactly {0,1}: masked relu accumulation (bit-exact)
            posr[0] += a.x * fmaxf(w.x, 0.f);  negr[0] += a.x * fmaxf(-w.x, 0.f);
            posr[1] += a.y * fmaxf(w.y, 0.f);  negr[1] += a.y * fmaxf(-w.y, 0.f);
            posr[2] += a.z * fmaxf(w.z, 0.f);  negr[2] += a.z * fmaxf(-w.z, 0.f);
            posr[3] += a.w * fmaxf(w.w, 0.f);  negr[3] += a.w * fmaxf(-w.w, 0.f);
        }
        __syncthreads();

        // --- Compaction: warp scans its own 4 columns into Ls ---
        int ncol[4];
        #pragma unroll
        for (int cc = 0; cc < 4; ++cc) {
            int j = warp * 4 + cc;
            int run = 0;
            #pragma unroll
            for (int base = 0; base < 128; base += 32) {
                unsigned char av = adjB[(base + lane) * 68 + j];  // conflict-free
                unsigned m = __ballot_sync(0xffffffffu, av != 0);
                if (av)
                    Ls[(j << 6) + run + __popc(m & ((1u << lane) - 1u))] =
                        (unsigned char)(base + lane);
                run += __popc(m);
            }
            ncol[cc] = run;
        }
        __syncwarp();   // warp reads its own Ls writes

        // --- Quad-pipelined gather, two independent add2 chains ---
        #pragma unroll
        for (int jj = 0; jj < 4; ++jj) {
            int j = warp * 4 + jj;
            int n = ncol[jj];
            const unsigned char* L = Ls + (j << 6);
            unsigned long long a0 = acc2[jj][0], a1 = acc2[jj][1];
            unsigned long long c0 = 0ull, c1 = 0ull;
            int k = 0;
            for (; k + 4 <= n; k += 4) {
                unsigned q = *(const unsigned*)(L + k);
                int i0x = q & 255, i1x = (q >> 8) & 255,
                    i2x = (q >> 16) & 255, i3x = q >> 24;
                ulonglong2 v0 = *(const ulonglong2*)&mwS[i0x * 128 + lane4];
                ulonglong2 v1 = *(const ulonglong2*)&mwS[i1x * 128 + lane4];
                ulonglong2 v2 = *(const ulonglong2*)&mwS[i2x * 128 + lane4];
                ulonglong2 v3 = *(const ulonglong2*)&mwS[i3x * 128 + lane4];
                add2(a0, v0.x); add2(a1, v0.y);
                add2(c0, v1.x); add2(c1, v1.y);
                add2(a0, v2.x); add2(a1, v2.y);
                add2(c0, v3.x); add2(c1, v3.y);
            }
            for (; k < n; ++k) {
                int i = L[k];
                ulonglong2 v = *(const ulonglong2*)&mwS[i * 128 + lane4];
                add2(a0, v.x); add2(a1, v.y);
            }
            add2(a0, c0); add2(a1, c1);
            acc2[jj][0] = a0; acc2[jj][1] = a1;
        }
    }

    // --- Deterministic pos/neg reduction (pbuf overlays dead mwS) ---
    __syncthreads();
    {
        int g = tid >> 4;        // 0..31
        #pragma unroll
        for (int c = 0; c < 4; ++c) {
            pbuf[g * 64 + jc * 4 + c]        = posr[c];
            pbuf[2048 + g * 64 + jc * 4 + c] = negr[c];
        }
    }
    __syncthreads();
    if (tid < 128) {
        int j = tid & 63;
        const float* src = pbuf + (tid < 64 ? 0 : 2048);
        float s = 0.f;
        #pragma unroll
        for (int g = 0; g < 32; ++g) s += src[g * 64 + j];
        if (tid < 64) posS[j] = s; else negS[j] = s;
    }
    __syncthreads();

    // --- Fused epilogue ---
    #pragma unroll
    for (int jj = 0; jj < 4; ++jj) {
        int gj = j0 + warp * 4 + jj;
        float xv = x[b * Nn + gj];
        float pj = posS[warp * 4 + jj];
        float nj = negS[warp * 4 + jj];
        int p = lane4;
        float2 u0 = unpack2(acc2[jj][0]);
        float2 u1 = unpack2(acc2[jj][1]);
        float4 o;
        o.x = fmaxf(xv * W1s[p + 0] + u0.x + pj * vps[p + 0] + nj * vns[p + 0] + cbs[p + 0], 0.f);
        o.y = fmaxf(xv * W1s[p + 1] + u0.y + pj * vps[p + 1] + nj * vns[p + 1] + cbs[p + 1], 0.f);
        o.z = fmaxf(xv * W1s[p + 2] + u1.x + pj * vps[p + 2] + nj * vns[p + 2] + cbs[p + 2], 0.f);
        o.w = fmaxf(xv * W1s[p + 3] + u1.y + pj * vps[p + 3] + nj * vns[p + 3] + cbs[p + 3], 0.f);
        *(float4*)&out[((size_t)b * Nn + gj) * Pn + p] = o;
    }
}

// ---------------------------------------------------------------------------
extern "C" void kernel_launch(void* const* d_in, const int* in_sizes, int n_in,
                              void* d_out, int out_size) {
    const float* x      = (const float*)d_in[0];
    const float* mu     = (const float*)d_in[1];
    const float* weight = (const float*)d_in[2];
    const float* adj    = (const float*)d_in[3];
    const float* W1     = (const float*)d_in[4];
    const float* b1     = (const float*)d_in[5];
    const float* W2     = (const float*)d_in[6];
    const float* b2     = (const float*)d_in[7];
    const float* W3     = (const float*)d_in[8];
    const float* b3     = (const float*)d_in[9];
    const float* theta4 = (const float*)d_in[10];
    float* out = (float*)d_out;

    const int smem_bytes = 78336 + 4 * 128 * 4 + 2 * 64 * 4;  // 80896 B
    static int configured = -1;
    if (configured < 0) {
        cudaFuncSetAttribute(agg_kernel, cudaFuncAttributeMaxDynamicSharedMemorySize,
                             smem_bytes);
        configured = 1;
    }

    mw_kernel<<<Bn * Nn / 64 + 1, 256>>>(mu, W2, W3, theta4, b1, b2, b3);
    dim3 grid(Nn / 64, Bn);
    agg_kernel<<<grid, 512, smem_bytes>>>(adj, weight, x, W1, out);
}